// round 5
// baseline (speedup 1.0000x reference)
#include <cuda_runtime.h>
#include <cstdint>

// InversePoseMatrixLayer: out = [R^T | -R^T t] for 4M poses (3x4 fp32 each).
//
// R4: TMA bulk copies (as R3) with 2x larger tiles: 512 poses = 24KB per
// block, 256 threads, 2 poses per thread (interleaved by 256 so both keep
// the conflict-free stride-3-float4 smem pattern). Halves block count
// (protocol overhead) and doubles in-flight bulk bytes per SM.

#define THREADS         256
#define POSES_PER_BLOCK 512
#define TILE_F4         (POSES_PER_BLOCK * 3)    // 1536 float4 = 24KB

__device__ __forceinline__ uint32_t smem_u32(const void* p) {
    uint32_t a;
    asm("{ .reg .u64 t; cvta.to.shared.u64 t, %1; cvt.u32.u64 %0, t; }"
        : "=r"(a) : "l"(p));
    return a;
}

__device__ __forceinline__ void invert_pose_inplace(float4* s, int slot) {
    const float4 r0 = s[slot + 0];   // (R00, R01, R02, t0)
    const float4 r1 = s[slot + 1];   // (R10, R11, R12, t1)
    const float4 r2 = s[slot + 2];   // (R20, R21, R22, t2)

    const float ti0 = -(r0.x * r0.w + r1.x * r1.w + r2.x * r2.w);
    const float ti1 = -(r0.y * r0.w + r1.y * r1.w + r2.y * r2.w);
    const float ti2 = -(r0.z * r0.w + r1.z * r1.w + r2.z * r2.w);

    s[slot + 0] = make_float4(r0.x, r1.x, r2.x, ti0);
    s[slot + 1] = make_float4(r0.y, r1.y, r2.y, ti1);
    s[slot + 2] = make_float4(r0.z, r1.z, r2.z, ti2);
}

__global__ __launch_bounds__(THREADS) void inverse_pose_kernel(
    const char* __restrict__ in, char* __restrict__ out, int n_poses)
{
    __shared__ __align__(128) float4 tile[TILE_F4];
    __shared__ __align__(8) uint64_t mbar;

    const int tid = threadIdx.x;
    const long long pose_base = (long long)blockIdx.x * POSES_PER_BLOCK;
    int poses_here = n_poses - (int)pose_base;
    if (poses_here > POSES_PER_BLOCK) poses_here = POSES_PER_BLOCK;
    const unsigned bytes = (unsigned)poses_here * 48u;   // multiple of 16

    const uint32_t s_tile = smem_u32(tile);
    const uint32_t s_mbar = smem_u32(&mbar);

    if (tid == 0) {
        asm volatile("mbarrier.init.shared.b64 [%0], %1;"
                     :: "r"(s_mbar), "r"(1u) : "memory");
    }
    __syncthreads();

    if (tid == 0) {
        asm volatile("mbarrier.arrive.expect_tx.shared.b64 _, [%0], %1;"
                     :: "r"(s_mbar), "r"(bytes) : "memory");
        asm volatile(
            "cp.async.bulk.shared::cta.global.mbarrier::complete_tx::bytes "
            "[%0], [%1], %2, [%3];"
            :: "r"(s_tile), "l"(in + pose_base * 48), "r"(bytes), "r"(s_mbar)
            : "memory");
    }

    // Wait for the bulk load (phase 0).
    {
        uint32_t done;
        asm volatile(
            "{\n\t"
            ".reg .pred p;\n\t"
            "mbarrier.try_wait.parity.shared.b64 p, [%1], %2;\n\t"
            "selp.b32 %0, 1, 0, p;\n\t"
            "}"
            : "=r"(done) : "r"(s_mbar), "r"(0u) : "memory");
        while (!done) {
            asm volatile(
                "{\n\t"
                ".reg .pred p;\n\t"
                "mbarrier.try_wait.parity.shared.b64 p, [%1], %2, 0x989680;\n\t"
                "selp.b32 %0, 1, 0, p;\n\t"
                "}"
                : "=r"(done) : "r"(s_mbar), "r"(0u) : "memory");
        }
    }

    // Two poses per thread, interleaved by 256 so both access sets keep the
    // conflict-free stride-3-float4 bank pattern.
    if (tid < poses_here)
        invert_pose_inplace(tile, 3 * tid);
    const int p2 = tid + 256;
    if (p2 < poses_here)
        invert_pose_inplace(tile, 3 * p2);

    // Make generic-proxy smem writes visible to the async proxy, then sync.
    asm volatile("fence.proxy.async.shared::cta;" ::: "memory");
    __syncthreads();

    if (tid == 0) {
        asm volatile(
            "cp.async.bulk.global.shared::cta.bulk_group [%0], [%1], %2;"
            :: "l"(out + pose_base * 48), "r"(s_tile), "r"(bytes)
            : "memory");
        asm volatile("cp.async.bulk.commit_group;" ::: "memory");
        // Keep the CTA (and its smem) alive until TMA has read the tile.
        asm volatile("cp.async.bulk.wait_group.read 0;" ::: "memory");
    }
}

extern "C" void kernel_launch(void* const* d_in, const int* in_sizes, int n_in,
                              void* d_out, int out_size)
{
    const char* in = (const char*)d_in[0];
    char* out = (char*)d_out;
    const int n_poses = in_sizes[0] / 12;   // 12 floats per pose

    const int blocks = (n_poses + POSES_PER_BLOCK - 1) / POSES_PER_BLOCK;
    inverse_pose_kernel<<<blocks, THREADS>>>(in, out, n_poses);
}